// round 8
// baseline (speedup 1.0000x reference)
#include <cuda_runtime.h>
#include <cstdint>

// ============================================================================
// SharedMatrix (butterfly block-sparse matmul) on GB300, PLAIN sm_103 target.
//   x : [8192, 4096] f32          (d_in[0])
//   w : [4096, 5, 256] f32        (d_in[1])
//   fi: [16, 5] int32             (d_in[2])
//   out:[8192, 4096] f32
//
// 16 GEMMs: M=8192, N=256, K=1280 via mma.sync.m16n8k8.tf32.
// R8 vs R7: two 128-thread CTAs per SM (independent barrier domains fill the
// per-iteration sync bubbles), CTA tile 128x128, 4 warps of 64x64 tiles
// (keeps R7's low LDSM traffic), 3x32KB stages, register ping-pong kept.
// ============================================================================

static constexpr int NKIT = 40;                    // 5 blocks x 8 chunks of k=32
static constexpr uint32_t A_BYTES = 16384;         // 128 x 32 x 4
static constexpr uint32_t B_BYTES = 16384;         // 128 x 32 x 4
static constexpr uint32_t STAGE_BYTES = A_BYTES + B_BYTES;      // 32KB
static constexpr uint32_t SMEM_TOTAL = 3 * STAGE_BYTES + 1024;  // 99328

// Repacked gathered tf32(RNA) weights, pre-swizzled 16KB SMEM images:
// g_Bp[((o*2+nh)*40+it)*4096 + swz(nl*128 + k*4)/4]   (32*40*16KB = 20.97 MB)
__device__ float g_Bp[32 * NKIT * 4096];

// ---------------------------------------------------------------------------
__device__ __forceinline__ uint32_t smem_u32(const void* p) {
    uint32_t a;
    asm("{ .reg .u64 t; cvta.to.shared.u64 t, %1; cvt.u32.u64 %0, t; }"
        : "=r"(a) : "l"(p));
    return a;
}
__device__ __forceinline__ void cpasync16(uint32_t dst, const float* src) {
    asm volatile("cp.async.cg.shared.global [%0], [%1], 16;"
                 :: "r"(dst), "l"(src) : "memory");
}
__device__ __forceinline__ void cp_commit() {
    asm volatile("cp.async.commit_group;" ::: "memory");
}
template <int N>
__device__ __forceinline__ void cp_wait() {
    asm volatile("cp.async.wait_group %0;" :: "n"(N) : "memory");
}
__device__ __forceinline__ void ldsm4(uint32_t* r, uint32_t a) {
    asm volatile("ldmatrix.sync.aligned.m8n8.x4.shared.b16 {%0,%1,%2,%3}, [%4];"
                 : "=r"(r[0]), "=r"(r[1]), "=r"(r[2]), "=r"(r[3]) : "r"(a));
}
__device__ __forceinline__ void mma_tf32(float* c, const uint32_t* a,
                                         uint32_t b0, uint32_t b1) {
    asm volatile(
        "mma.sync.aligned.m16n8k8.row.col.f32.tf32.tf32.f32 "
        "{%0,%1,%2,%3}, {%4,%5,%6,%7}, {%8,%9}, {%0,%1,%2,%3};"
        : "+f"(c[0]), "+f"(c[1]), "+f"(c[2]), "+f"(c[3])
        : "r"(a[0]), "r"(a[1]), "r"(a[2]), "r"(a[3]), "r"(b0), "r"(b1));
}

// ---------------------------------------------------------------------------
// repack: gather + transpose + RNA-round weights into pre-swizzled 16KB tiles
//   grid: (ntile=8, kchunk=8, o*5+a=80), block (32, 8)
// ---------------------------------------------------------------------------
__global__ void __launch_bounds__(256, 4)
repack_kernel(const float* __restrict__ w, const int* __restrict__ fi) {
    const int oa = blockIdx.z;
    const int o = oa / 5, a = oa % 5;
    const int f = fi[o * 5 + a];
    const int g = f / 5, slot = f % 5;
    const int k0 = blockIdx.y * 32;
    const int n0 = blockIdx.x * 32;
    const int c = blockIdx.y;
    const int nh = n0 >> 7;

    __shared__ float t[32][33];
    const int tx = threadIdx.x, ty = threadIdx.y;

    #pragma unroll
    for (int i = 0; i < 4; ++i) {
        int k = ty + i * 8;
        float v = w[((size_t)(g * 256 + k0 + k) * 5 + slot) * 256 + n0 + tx];
        uint32_t u;
        asm("cvt.rna.tf32.f32 %0, %1;" : "=r"(u) : "f"(v));
        t[k][tx] = __uint_as_float(u);
    }
    __syncthreads();

    float* tile = g_Bp + ((size_t)(o * 2 + nh) * NKIT + a * 8 + c) * 4096;
    #pragma unroll
    for (int i = 0; i < 4; ++i) {
        int nl = (n0 & 127) + ty + i * 8;
        uint32_t off = (uint32_t)nl * 128u + (uint32_t)tx * 4u;
        uint32_t swz = off ^ ((off >> 3) & 0x70u);
        tile[swz >> 2] = t[tx][ty + i * 8];
    }
}

// ---------------------------------------------------------------------------
// GEMM: grid (o*2+nh=32, mtile=64), 128 threads, CTA tile 128(M) x 128(N)
//   4 warps in 2(m) x 2(n) grid of 64x64 warp tiles; 2 CTAs per SM.
// ---------------------------------------------------------------------------
__global__ void __launch_bounds__(128, 2)
gemm_kernel(const float* __restrict__ x, const int* __restrict__ fi,
            float* __restrict__ out) {
    extern __shared__ char smem_raw[];
    const uint32_t sb = (smem_u32(smem_raw) + 1023u) & ~1023u;
    const int tid = (int)threadIdx.x;
    const int wid = tid >> 5;
    const int lane = tid & 31;
    const int o = (int)blockIdx.x >> 1;
    const int nh = (int)blockIdx.x & 1;
    const int m_base = (int)blockIdx.y * 128;
    const int warp_m = wid >> 1;   // 0..1  (64 rows each)
    const int warp_n = wid & 1;    // 0..1  (64 cols each)

    int colf[5];
    #pragma unroll
    for (int a = 0; a < 5; ++a) colf[a] = (fi[o * 5 + a] / 5) << 8;

    // ---- producer addressing (all 128 threads) ----
    // A: 128 rows x 8 16B-segs = 1024 segs -> 8 per thread (one row each)
    const int arow = tid;                      // 0..127
    const float* xrow = x + (size_t)(m_base + arow) * 4096;
    const uint32_t adst_base = (uint32_t)arow * 128u;
    const uint32_t axor = (uint32_t)(arow & 7) << 4;
    // B: 16KB image = 1024 segs -> 8 per thread (raw copy)
    const float* bsrc0 = g_Bp + (size_t)blockIdx.x * NKIT * 4096 + tid * 4;

    auto issue = [&](int it, uint32_t s) {
        const uint32_t st = sb + s * STAGE_BYTES;
        const int col = colf[it >> 3] + (it & 7) * 32;
        const float* asrc = xrow + col;
        #pragma unroll
        for (int j = 0; j < 8; ++j) {
            uint32_t doff = (((uint32_t)j * 16u) ^ axor);
            cpasync16(st + adst_base + doff, asrc + j * 4);
        }
        const float* bsrc = bsrc0 + (size_t)it * 4096;
        #pragma unroll
        for (int j = 0; j < 8; ++j)
            cpasync16(st + A_BYTES + (uint32_t)tid * 16u + (uint32_t)j * 2048u,
                      bsrc + j * 512);
        cp_commit();
    };

    // ---- consumer lane addressing ----
    const int a_tile = lane >> 3;              // 0..3
    const int a_row_l = ((a_tile & 1) << 3) + (lane & 7);
    const int a_ktile = a_tile >> 1;           // 0..1 (k half of 16)
    const int b_khalf = (lane >> 3) & 1;
    const int b_row_l = (((lane >> 4) & 1) << 3) + (lane & 7);

    const uint32_t a_warp_off = (uint32_t)(warp_m * 64) * 128u;
    const uint32_t b_warp_off = A_BYTES + (uint32_t)(warp_n * 64) * 128u;

    float c[4][8][4];
    #pragma unroll
    for (int mi = 0; mi < 4; ++mi)
        #pragma unroll
        for (int ni = 0; ni < 8; ++ni)
            #pragma unroll
            for (int q = 0; q < 4; ++q) c[mi][ni][q] = 0.0f;

    uint32_t af[2][4][4];   // [pingpong][mi][frag]
    uint32_t bf[2][4][4];   // [pingpong][ni2][frag]

    auto load_frags = [&](uint32_t st, int ks, int pb) {
        const uint32_t abw = st + a_warp_off;
        const uint32_t bbw = st + b_warp_off;
        #pragma unroll
        for (int mi = 0; mi < 4; ++mi) {
            int row = mi * 16 + a_row_l;
            uint32_t off = (uint32_t)((ks * 2 + a_ktile) * 16) ^
                           ((uint32_t)(row & 7) << 4);
            ldsm4(af[pb][mi], abw + (uint32_t)row * 128u + off);
        }
        #pragma unroll
        for (int ni2 = 0; ni2 < 4; ++ni2) {
            int n = ni2 * 16 + b_row_l;
            uint32_t off = (uint32_t)((ks * 2 + b_khalf) * 16) ^
                           ((uint32_t)(n & 7) << 4);
            ldsm4(bf[pb][ni2], bbw + (uint32_t)n * 128u + off);
        }
    };

    auto mma_group = [&](int pb) {
        #pragma unroll
        for (int mi = 0; mi < 4; ++mi)
            #pragma unroll
            for (int ni = 0; ni < 8; ++ni) {
                const uint32_t* bp = &bf[pb][ni >> 1][(ni & 1) * 2];
                mma_tf32(c[mi][ni], af[pb][mi], bp[0], bp[1]);
            }
    };

    // prologue: fill 2 of 3 stages, land frags for stage 0 / ks 0
    issue(0, 0); issue(1, 1);
    cp_wait<1>();
    __syncthreads();
    load_frags(sb, 0, 0);

    int buf = 0;
    for (int it = 0; it < NKIT; ++it) {
        const uint32_t st = sb + (uint32_t)buf * STAGE_BYTES;

        if (it + 2 < NKIT) {
            int nb = buf + 2; if (nb >= 3) nb -= 3;
            issue(it + 2, (uint32_t)nb);
        } else {
            cp_commit();   // keep group numbering advancing
        }

        // ks 0..3 with register ping-pong: load ks+1 while MMAing ks
        load_frags(st, 1, 1);  mma_group(0);
        load_frags(st, 2, 0);  mma_group(1);
        load_frags(st, 3, 1);  mma_group(0);
        mma_group(1);

        int nxt = buf + 1; if (nxt == 3) nxt = 0;
        cp_wait<1>();
        __syncthreads();
        if (it + 1 < NKIT)
            load_frags(sb + (uint32_t)nxt * STAGE_BYTES, 0, 0);
        buf = nxt;
    }

    // ---- epilogue: direct stores ----
    const int g = lane >> 2, t4 = lane & 3;
    const int row0 = m_base + warp_m * 64 + g;
    const int col0 = o * 256 + nh * 128 + warp_n * 64 + t4 * 2;
    #pragma unroll
    for (int mi = 0; mi < 4; ++mi) {
        #pragma unroll
        for (int ni = 0; ni < 8; ++ni) {
            float* p0 = out + (size_t)(row0 + mi * 16) * 4096 + col0 + ni * 8;
            float* p1 = p0 + 8 * 4096;
            *reinterpret_cast<float2*>(p0) =
                make_float2(c[mi][ni][0], c[mi][ni][1]);
            *reinterpret_cast<float2*>(p1) =
                make_float2(c[mi][ni][2], c[mi][ni][3]);
        }
    }
}

// ---------------------------------------------------------------------------
extern "C" void kernel_launch(void* const* d_in, const int* in_sizes, int n_in,
                              void* d_out, int out_size) {
    const float* x  = (const float*)d_in[0];
    const float* w  = (const float*)d_in[1];
    const int*   fi = (const int*)d_in[2];
    float* out = (float*)d_out;

    repack_kernel<<<dim3(8, 8, 80), dim3(32, 8)>>>(w, fi);

    cudaFuncSetAttribute(gemm_kernel,
                         cudaFuncAttributeMaxDynamicSharedMemorySize, SMEM_TOTAL);
    gemm_kernel<<<dim3(32, 64), 128, SMEM_TOTAL>>>(x, fi, out);
}

// round 9
// speedup vs baseline: 1.2213x; 1.2213x over previous
#include <cuda_runtime.h>
#include <cstdint>

// ============================================================================
// SharedMatrix (butterfly block-sparse matmul) on GB300, PLAIN sm_103 target.
//   x : [8192, 4096] f32          (d_in[0])
//   w : [4096, 5, 256] f32        (d_in[1])
//   fi: [16, 5] int32             (d_in[2])
//   out:[8192, 4096] f32
//
// 16 GEMMs: M=8192, N=256, K=1280 via mma.sync.m16n8k8.tf32.
// R9 vs R7 (R8 reverted): k=64 stages -> 20 iterations instead of 40, halving
// per-iteration sync overhead (barrier + cp_wait + post-barrier ldsm latency).
// 2 stages x 96KB, CTA tile 128x256, 8 warps of 64x64, register ping-pong.
// ============================================================================

static constexpr int NKIT = 20;                    // k-iters of 64 (5 blocks x 4)
static constexpr uint32_t A_BYTES = 32768;         // 128 x 64 x 4 (two 16KB halves)
static constexpr uint32_t B_BYTES = 65536;         // 256 x 64 x 4 (two 32KB images)
static constexpr uint32_t STAGE_BYTES = A_BYTES + B_BYTES;      // 96KB
static constexpr uint32_t SMEM_TOTAL = 2 * STAGE_BYTES + 1024;  // 197632

// Repacked gathered tf32(RNA) weights, pre-swizzled 32KB SMEM images:
// g_Bp[(o*40+c32)*8192 + swz(n*128 + k*4)/4]   (16*40*32KB = 20.97 MB)
__device__ float g_Bp[16 * 40 * 8192];

// ---------------------------------------------------------------------------
__device__ __forceinline__ uint32_t smem_u32(const void* p) {
    uint32_t a;
    asm("{ .reg .u64 t; cvta.to.shared.u64 t, %1; cvt.u32.u64 %0, t; }"
        : "=r"(a) : "l"(p));
    return a;
}
__device__ __forceinline__ void cpasync16(uint32_t dst, const float* src) {
    asm volatile("cp.async.cg.shared.global [%0], [%1], 16;"
                 :: "r"(dst), "l"(src) : "memory");
}
__device__ __forceinline__ void cp_commit() {
    asm volatile("cp.async.commit_group;" ::: "memory");
}
template <int N>
__device__ __forceinline__ void cp_wait() {
    asm volatile("cp.async.wait_group %0;" :: "n"(N) : "memory");
}
__device__ __forceinline__ void ldsm4(uint32_t* r, uint32_t a) {
    asm volatile("ldmatrix.sync.aligned.m8n8.x4.shared.b16 {%0,%1,%2,%3}, [%4];"
                 : "=r"(r[0]), "=r"(r[1]), "=r"(r[2]), "=r"(r[3]) : "r"(a));
}
__device__ __forceinline__ void mma_tf32(float* c, const uint32_t* a,
                                         uint32_t b0, uint32_t b1) {
    asm volatile(
        "mma.sync.aligned.m16n8k8.row.col.f32.tf32.tf32.f32 "
        "{%0,%1,%2,%3}, {%4,%5,%6,%7}, {%8,%9}, {%0,%1,%2,%3};"
        : "+f"(c[0]), "+f"(c[1]), "+f"(c[2]), "+f"(c[3])
        : "r"(a[0]), "r"(a[1]), "r"(a[2]), "r"(a[3]), "r"(b0), "r"(b1));
}

// ---------------------------------------------------------------------------
// repack: gather + transpose + RNA-round weights into pre-swizzled 32KB tiles
//   grid: (ntile=8, kchunk=8, o*5+a=80), block (32, 8)
// ---------------------------------------------------------------------------
__global__ void __launch_bounds__(256, 4)
repack_kernel(const float* __restrict__ w, const int* __restrict__ fi) {
    const int oa = blockIdx.z;
    const int o = oa / 5, a = oa % 5;
    const int f = fi[o * 5 + a];
    const int g = f / 5, slot = f % 5;
    const int k0 = blockIdx.y * 32;
    const int n0 = blockIdx.x * 32;
    const int c = blockIdx.y;

    __shared__ float t[32][33];
    const int tx = threadIdx.x, ty = threadIdx.y;

    #pragma unroll
    for (int i = 0; i < 4; ++i) {
        int k = ty + i * 8;
        float v = w[((size_t)(g * 256 + k0 + k) * 5 + slot) * 256 + n0 + tx];
        uint32_t u;
        asm("cvt.rna.tf32.f32 %0, %1;" : "=r"(u) : "f"(v));
        t[k][tx] = __uint_as_float(u);
    }
    __syncthreads();

    float* tile = g_Bp + ((size_t)o * 40 + a * 8 + c) * 8192;
    #pragma unroll
    for (int i = 0; i < 4; ++i) {
        int n = n0 + ty + i * 8;
        uint32_t off = (uint32_t)n * 128u + (uint32_t)tx * 4u;
        uint32_t swz = off ^ ((off >> 3) & 0x70u);
        tile[swz >> 2] = t[tx][ty + i * 8];
    }
}

// ---------------------------------------------------------------------------
// GEMM: grid (o=16, mtile=64), 256 threads, CTA tile 128(M) x 256(N)
//   8 warps in 2(m) x 4(n) grid of 64x64 warp tiles; k=64 per iteration.
// ---------------------------------------------------------------------------
__global__ void __launch_bounds__(256, 1)
gemm_kernel(const float* __restrict__ x, const int* __restrict__ fi,
            float* __restrict__ out) {
    extern __shared__ char smem_raw[];
    const uint32_t sb = (smem_u32(smem_raw) + 1023u) & ~1023u;
    const int tid = (int)threadIdx.x;
    const int wid = tid >> 5;
    const int lane = tid & 31;
    const int o = (int)blockIdx.x;
    const int m_base = (int)blockIdx.y * 128;
    const int warp_m = wid >> 2;   // 0..1  (64 rows each)
    const int warp_n = wid & 3;    // 0..3  (64 cols each)

    int colf[5];
    #pragma unroll
    for (int a = 0; a < 5; ++a) colf[a] = (fi[o * 5 + a] / 5) << 8;

    // ---- producer addressing (all 256 threads) ----
    // A: two 16KB halves, each [128 rows][32 floats] SW128; 8 segs/thread.
    const int arow = tid >> 1;                 // 0..127
    const int asub = (tid & 1) * 4;            // segments asub..asub+3 (of 8)
    const float* xrow = x + (size_t)(m_base + arow) * 4096;
    const uint32_t adst_base = (uint32_t)arow * 128u;
    const uint32_t axor = (uint32_t)(arow & 7) << 4;
    // B: two consecutive 32KB images raw-copied; 16 segs/thread.
    const float* bsrc0 = g_Bp + (size_t)o * 40 * 8192 + tid * 4;

    auto issue = [&](int it, uint32_t s) {
        const uint32_t st = sb + s * STAGE_BYTES;
        const int col = colf[it >> 2] + (it & 3) * 64;
        #pragma unroll
        for (int h = 0; h < 2; ++h) {
            const float* asrc = xrow + col + h * 32 + asub * 4;
            const uint32_t ad = st + (uint32_t)h * 16384u + adst_base;
            #pragma unroll
            for (int j = 0; j < 4; ++j) {
                uint32_t doff = (((uint32_t)(asub + j) * 16u) ^ axor);
                cpasync16(ad + doff, asrc + j * 4);
            }
        }
        #pragma unroll
        for (int h = 0; h < 2; ++h) {
            const float* bsrc = bsrc0 + (size_t)(it * 2 + h) * 8192;
            const uint32_t bd = st + A_BYTES + (uint32_t)h * 32768u +
                                (uint32_t)tid * 16u;
            #pragma unroll
            for (int j = 0; j < 8; ++j)
                cpasync16(bd + (uint32_t)j * 4096u, bsrc + j * 1024);
        }
        cp_commit();
    };

    // ---- consumer lane addressing ----
    const int a_tile = lane >> 3;              // 0..3
    const int a_row_l = ((a_tile & 1) << 3) + (lane & 7);
    const int a_ktile = a_tile >> 1;           // 0..1 (k half of 16)
    const int b_khalf = (lane >> 3) & 1;
    const int b_row_l = (((lane >> 4) & 1) << 3) + (lane & 7);

    const uint32_t a_warp_off = (uint32_t)(warp_m * 64) * 128u;
    const uint32_t b_warp_off = A_BYTES + (uint32_t)(warp_n * 64) * 128u;

    float c[4][8][4];
    #pragma unroll
    for (int mi = 0; mi < 4; ++mi)
        #pragma unroll
        for (int ni = 0; ni < 8; ++ni)
            #pragma unroll
            for (int q = 0; q < 4; ++q) c[mi][ni][q] = 0.0f;

    uint32_t af[2][4][4];   // [pingpong][mi][frag]
    uint32_t bf[2][4][4];   // [pingpong][ni2][frag]

    // ks = 0..7 within a stage: ksub = ks>>2 selects 16KB A half / 32KB B img,
    // kw = ks&3 selects k-offset within the 128B row.
    auto load_frags = [&](uint32_t st, int ks, int pb) {
        const int ksub = ks >> 2, kw = ks & 3;
        const uint32_t abw = st + (uint32_t)ksub * 16384u + a_warp_off;
        const uint32_t bbw = st + (uint32_t)ksub * 32768u + b_warp_off;
        #pragma unroll
        for (int mi = 0; mi < 4; ++mi) {
            int row = mi * 16 + a_row_l;
            uint32_t off = (uint32_t)((kw * 2 + a_ktile) * 16) ^
                           ((uint32_t)(row & 7) << 4);
            ldsm4(af[pb][mi], abw + (uint32_t)row * 128u + off);
        }
        #pragma unroll
        for (int ni2 = 0; ni2 < 4; ++ni2) {
            int n = ni2 * 16 + b_row_l;
            uint32_t off = (uint32_t)((kw * 2 + b_khalf) * 16) ^
                           ((uint32_t)(n & 7) << 4);
            ldsm4(bf[pb][ni2], bbw + (uint32_t)n * 128u + off);
        }
    };

    auto mma_group = [&](int pb) {
        #pragma unroll
        for (int mi = 0; mi < 4; ++mi)
            #pragma unroll
            for (int ni = 0; ni < 8; ++ni) {
                const uint32_t* bp = &bf[pb][ni >> 1][(ni & 1) * 2];
                mma_tf32(c[mi][ni], af[pb][mi], bp[0], bp[1]);
            }
    };

    // prologue: fill stage 0, land frags for ks 0
    issue(0, 0);
    cp_wait<0>();
    __syncthreads();
    load_frags(sb, 0, 0);

    for (int it = 0; it < NKIT; ++it) {
        const uint32_t st = sb + (uint32_t)(it & 1) * STAGE_BYTES;

        if (it + 1 < NKIT) issue(it + 1, (uint32_t)((it + 1) & 1));

        // 8 ks sub-steps with register ping-pong
        load_frags(st, 1, 1);  mma_group(0);
        load_frags(st, 2, 0);  mma_group(1);
        load_frags(st, 3, 1);  mma_group(0);
        load_frags(st, 4, 0);  mma_group(1);
        load_frags(st, 5, 1);  mma_group(0);
        load_frags(st, 6, 0);  mma_group(1);
        load_frags(st, 7, 1);  mma_group(0);
        mma_group(1);

        cp_wait<0>();
        __syncthreads();
        if (it + 1 < NKIT)
            load_frags(sb + (uint32_t)((it + 1) & 1) * STAGE_BYTES, 0, 0);
    }

    // ---- epilogue: direct stores ----
    const int g = lane >> 2, t4 = lane & 3;
    const int row0 = m_base + warp_m * 64 + g;
    const int col0 = o * 256 + warp_n * 64 + t4 * 2;
    #pragma unroll
    for (int mi = 0; mi < 4; ++mi) {
        #pragma unroll
        for (int ni = 0; ni < 8; ++ni) {
            float* p0 = out + (size_t)(row0 + mi * 16) * 4096 + col0 + ni * 8;
            float* p1 = p0 + 8 * 4096;
            *reinterpret_cast<float2*>(p0) =
                make_float2(c[mi][ni][0], c[mi][ni][1]);
            *reinterpret_cast<float2*>(p1) =
                make_float2(c[mi][ni][2], c[mi][ni][3]);
        }
    }
}

// ---------------------------------------------------------------------------
extern "C" void kernel_launch(void* const* d_in, const int* in_sizes, int n_in,
                              void* d_out, int out_size) {
    const float* x  = (const float*)d_in[0];
    const float* w  = (const float*)d_in[1];
    const int*   fi = (const int*)d_in[2];
    float* out = (float*)d_out;

    repack_kernel<<<dim3(8, 8, 80), dim3(32, 8)>>>(w, fi);

    cudaFuncSetAttribute(gemm_kernel,
                         cudaFuncAttributeMaxDynamicSharedMemorySize, SMEM_TOTAL);
    gemm_kernel<<<dim3(16, 64), 256, SMEM_TOTAL>>>(x, fi, out);
}

// round 10
// speedup vs baseline: 1.3892x; 1.1375x over previous
#include <cuda_runtime.h>
#include <cstdint>

// ============================================================================
// SharedMatrix (butterfly block-sparse matmul) on GB300, PLAIN sm_103 target.
//   x : [8192, 4096] f32          (d_in[0])
//   w : [4096, 5, 256] f32        (d_in[1])
//   fi: [16, 5] int32             (d_in[2])
//   out:[8192, 4096] f32
//
// 16 GEMMs: M=8192, N=256, K=1280 via mma.sync.m16n8k8.tf32.
// R10 = R7 (best: 365us, tensor 79%) with the per-iteration barrier hoisted
// under queued tensor work: wait+syncthreads execute while 2 mma groups
// (~1024 SMSP-cyc) are still in the tensor queue, hiding barrier/wait jitter.
// 4 stages x 48KB, CTA 128x256, 8 warps of 64x64, register ping-pong.
// ============================================================================

static constexpr int NKIT = 40;                    // 5 blocks x 8 chunks of k=32
static constexpr uint32_t A_BYTES = 16384;         // 128 x 32 x 4
static constexpr uint32_t B_BYTES = 32768;         // 256 x 32 x 4
static constexpr uint32_t STAGE_BYTES = A_BYTES + B_BYTES;      // 48KB
static constexpr uint32_t SMEM_TOTAL = 4 * STAGE_BYTES + 1024;  // 197632

// Repacked gathered tf32(RNA) weights, pre-swizzled 32KB SMEM images:
// g_Bp[(o*40+it)*8192 + swz(n*128 + k*4)/4]   (16*40*32KB = 20.97 MB)
__device__ float g_Bp[16 * NKIT * 8192];

// ---------------------------------------------------------------------------
__device__ __forceinline__ uint32_t smem_u32(const void* p) {
    uint32_t a;
    asm("{ .reg .u64 t; cvta.to.shared.u64 t, %1; cvt.u32.u64 %0, t; }"
        : "=r"(a) : "l"(p));
    return a;
}
__device__ __forceinline__ void cpasync16(uint32_t dst, const float* src) {
    asm volatile("cp.async.cg.shared.global [%0], [%1], 16;"
                 :: "r"(dst), "l"(src) : "memory");
}
__device__ __forceinline__ void cp_commit() {
    asm volatile("cp.async.commit_group;" ::: "memory");
}
template <int N>
__device__ __forceinline__ void cp_wait() {
    asm volatile("cp.async.wait_group %0;" :: "n"(N) : "memory");
}
__device__ __forceinline__ void ldsm4(uint32_t* r, uint32_t a) {
    asm volatile("ldmatrix.sync.aligned.m8n8.x4.shared.b16 {%0,%1,%2,%3}, [%4];"
                 : "=r"(r[0]), "=r"(r[1]), "=r"(r[2]), "=r"(r[3]) : "r"(a));
}
__device__ __forceinline__ void mma_tf32(float* c, const uint32_t* a,
                                         uint32_t b0, uint32_t b1) {
    asm volatile(
        "mma.sync.aligned.m16n8k8.row.col.f32.tf32.tf32.f32 "
        "{%0,%1,%2,%3}, {%4,%5,%6,%7}, {%8,%9}, {%0,%1,%2,%3};"
        : "+f"(c[0]), "+f"(c[1]), "+f"(c[2]), "+f"(c[3])
        : "r"(a[0]), "r"(a[1]), "r"(a[2]), "r"(a[3]), "r"(b0), "r"(b1));
}

// ---------------------------------------------------------------------------
// repack: gather + transpose + RNA-round weights into pre-swizzled 32KB tiles
//   grid: (ntile=8, kchunk=8, o*5+a=80), block (32, 8)
// ---------------------------------------------------------------------------
__global__ void __launch_bounds__(256, 4)
repack_kernel(const float* __restrict__ w, const int* __restrict__ fi) {
    const int oa = blockIdx.z;
    const int o = oa / 5, a = oa % 5;
    const int f = fi[o * 5 + a];
    const int g = f / 5, slot = f % 5;
    const int k0 = blockIdx.y * 32;
    const int n0 = blockIdx.x * 32;
    const int c = blockIdx.y;

    __shared__ float t[32][33];
    const int tx = threadIdx.x, ty = threadIdx.y;

    #pragma unroll
    for (int i = 0; i < 4; ++i) {
        int k = ty + i * 8;
        float v = w[((size_t)(g * 256 + k0 + k) * 5 + slot) * 256 + n0 + tx];
        uint32_t u;
        asm("cvt.rna.tf32.f32 %0, %1;" : "=r"(u) : "f"(v));
        t[k][tx] = __uint_as_float(u);
    }
    __syncthreads();

    float* tile = g_Bp + ((size_t)o * NKIT + a * 8 + c) * 8192;
    #pragma unroll
    for (int i = 0; i < 4; ++i) {
        int n = n0 + ty + i * 8;
        uint32_t off = (uint32_t)n * 128u + (uint32_t)tx * 4u;
        uint32_t swz = off ^ ((off >> 3) & 0x70u);
        tile[swz >> 2] = t[tx][ty + i * 8];
    }
}

// ---------------------------------------------------------------------------
// GEMM: grid (o=16, mtile=64), 256 threads, CTA tile 128(M) x 256(N)
//   8 warps in 2(m) x 4(n) grid of 64x64 warp tiles; barrier under MMA queue.
// ---------------------------------------------------------------------------
__global__ void __launch_bounds__(256, 1)
gemm_kernel(const float* __restrict__ x, const int* __restrict__ fi,
            float* __restrict__ out) {
    extern __shared__ char smem_raw[];
    const uint32_t sb = (smem_u32(smem_raw) + 1023u) & ~1023u;
    const int tid = (int)threadIdx.x;
    const int wid = tid >> 5;
    const int lane = tid & 31;
    const int o = (int)blockIdx.x;
    const int m_base = (int)blockIdx.y * 128;
    const int warp_m = wid >> 2;   // 0..1  (64 rows each)
    const int warp_n = wid & 3;    // 0..3  (64 cols each)

    int colf[5];
    #pragma unroll
    for (int a = 0; a < 5; ++a) colf[a] = (fi[o * 5 + a] / 5) << 8;

    // ---- producer addressing (all 256 threads) ----
    const int arow = tid >> 1;                 // 0..127
    const int asub = (tid & 1) * 4;            // segments asub..asub+3 (of 8)
    const float* xrow = x + (size_t)(m_base + arow) * 4096;
    const uint32_t adst_base = (uint32_t)arow * 128u;
    const uint32_t axor = (uint32_t)(arow & 7) << 4;
    const float* bsrc0 = g_Bp + (size_t)o * NKIT * 8192 + tid * 4;

    auto issue = [&](int it, uint32_t s) {
        const uint32_t st = sb + s * STAGE_BYTES;
        const int col = colf[it >> 3] + (it & 7) * 32;
        const float* asrc = xrow + col + asub * 4;
        #pragma unroll
        for (int j = 0; j < 4; ++j) {
            uint32_t doff = (((uint32_t)(asub + j) * 16u) ^ axor);
            cpasync16(st + adst_base + doff, asrc + j * 4);
        }
        const float* bsrc = bsrc0 + (size_t)it * 8192;
        #pragma unroll
        for (int j = 0; j < 8; ++j)
            cpasync16(st + A_BYTES + (uint32_t)tid * 16u + (uint32_t)j * 4096u,
                      bsrc + j * 1024);
        cp_commit();
    };

    // ---- consumer lane addressing ----
    const int a_tile = lane >> 3;              // 0..3
    const int a_row_l = ((a_tile & 1) << 3) + (lane & 7);
    const int a_ktile = a_tile >> 1;           // 0..1 (k half of 16)
    const int b_khalf = (lane >> 3) & 1;
    const int b_row_l = (((lane >> 4) & 1) << 3) + (lane & 7);

    const uint32_t a_warp_off = (uint32_t)(warp_m * 64) * 128u;
    const uint32_t b_warp_off = A_BYTES + (uint32_t)(warp_n * 64) * 128u;

    float c[4][8][4];
    #pragma unroll
    for (int mi = 0; mi < 4; ++mi)
        #pragma unroll
        for (int ni = 0; ni < 8; ++ni)
            #pragma unroll
            for (int q = 0; q < 4; ++q) c[mi][ni][q] = 0.0f;

    uint32_t af[2][4][4];   // [pingpong][mi][frag]
    uint32_t bf[2][4][4];   // [pingpong][ni2][frag]

    auto load_frags = [&](uint32_t st, int ks, int pb) {
        const uint32_t abw = st + a_warp_off;
        const uint32_t bbw = st + b_warp_off;
        #pragma unroll
        for (int mi = 0; mi < 4; ++mi) {
            int row = mi * 16 + a_row_l;
            uint32_t off = (uint32_t)((ks * 2 + a_ktile) * 16) ^
                           ((uint32_t)(row & 7) << 4);
            ldsm4(af[pb][mi], abw + (uint32_t)row * 128u + off);
        }
        #pragma unroll
        for (int ni2 = 0; ni2 < 4; ++ni2) {
            int n = ni2 * 16 + b_row_l;
            uint32_t off = (uint32_t)((ks * 2 + b_khalf) * 16) ^
                           ((uint32_t)(n & 7) << 4);
            ldsm4(bf[pb][ni2], bbw + (uint32_t)n * 128u + off);
        }
    };

    auto mma_group = [&](int pb) {
        #pragma unroll
        for (int mi = 0; mi < 4; ++mi)
            #pragma unroll
            for (int ni = 0; ni < 8; ++ni) {
                const uint32_t* bp = &bf[pb][ni >> 1][(ni & 1) * 2];
                mma_tf32(c[mi][ni], af[pb][mi], bp[0], bp[1]);
            }
    };

    // prologue: fill 3 stages, land frags for stage 0 / ks 0
    issue(0, 0); issue(1, 1); issue(2, 2);
    cp_wait<2>();
    __syncthreads();
    load_frags(sb, 0, 0);

    #pragma unroll 4
    for (int it = 0; it < NKIT; ++it) {
        const uint32_t st = sb + (uint32_t)(it & 3) * STAGE_BYTES;

        // entry invariant: pb0 holds ks0 frags of stage it
        load_frags(st, 1, 1);                 // ks1 -> pb1
        mma_group(0);                         // ks0

        if (it + 3 < NKIT) issue(it + 3, (uint32_t)((it + 3) & 3));
        else cp_commit();                     // keep group numbering advancing

        load_frags(st, 2, 0);                 // ks2 -> pb0
        mma_group(1);                         // ks1
        load_frags(st, 3, 1);                 // ks3 -> pb1

        // barrier hidden under the ks2+ks3 tensor queue (~1024 SMSP-cyc):
        cp_wait<2>();                         // stage it+1 landed (own groups)
        __syncthreads();                      // cross-thread visibility + reuse

        mma_group(0);                         // ks2 (regs loaded pre-barrier)
        if (it + 1 < NKIT)
            load_frags(sb + (uint32_t)((it + 1) & 3) * STAGE_BYTES, 0, 0);
        mma_group(1);                         // ks3
    }

    // ---- epilogue: direct stores ----
    const int g = lane >> 2, t4 = lane & 3;
    const int row0 = m_base + warp_m * 64 + g;
    const int col0 = o * 256 + warp_n * 64 + t4 * 2;
    #pragma unroll
    for (int mi = 0; mi < 4; ++mi) {
        #pragma unroll
        for (int ni = 0; ni < 8; ++ni) {
            float* p0 = out + (size_t)(row0 + mi * 16) * 4096 + col0 + ni * 8;
            float* p1 = p0 + 8 * 4096;
            *reinterpret_cast<float2*>(p0) =
                make_float2(c[mi][ni][0], c[mi][ni][1]);
            *reinterpret_cast<float2*>(p1) =
                make_float2(c[mi][ni][2], c[mi][ni][3]);
        }
    }
}

// ---------------------------------------------------------------------------
extern "C" void kernel_launch(void* const* d_in, const int* in_sizes, int n_in,
                              void* d_out, int out_size) {
    const float* x  = (const float*)d_in[0];
    const float* w  = (const float*)d_in[1];
    const int*   fi = (const int*)d_in[2];
    float* out = (float*)d_out;

    repack_kernel<<<dim3(8, 8, 80), dim3(32, 8)>>>(w, fi);

    cudaFuncSetAttribute(gemm_kernel,
                         cudaFuncAttributeMaxDynamicSharedMemorySize, SMEM_TOTAL);
    gemm_kernel<<<dim3(16, 64), 256, SMEM_TOTAL>>>(x, fi, out);
}

// round 13
// speedup vs baseline: 2.1347x; 1.5366x over previous
#include <cuda_runtime.h>
#include <cuda_fp16.h>
#include <cstdint>

// ============================================================================
// SharedMatrix (butterfly block-sparse matmul) on GB300, PLAIN sm_103 target.
//   x : [8192, 4096] f32          (d_in[0])
//   w : [4096, 5, 256] f32        (d_in[1])
//   fi: [16, 5] int32             (d_in[2])
//   out:[8192, 4096] f32
//
// 16 GEMMs: M=8192, N=256, K=1280.
// R13 = R12 with the convert_kernel destination-indexing bug fixed
// (each thread writes 2 uint4 -> stride must be tid*2, not tid).
// fp16 mma.sync.m16n8k16 (2x tf32 rate), x pre-converted to fp16 (RN),
// weights repacked to fp16 pre-swizzled images. Stage = k64 (48KB),
// NKIT=20, 4 stages, barrier-under-queue loop.
// ============================================================================

static constexpr int NKIT = 20;                    // 5 blocks x 4 chunks of k=64
static constexpr uint32_t A_BYTES = 16384;         // 128 x 64 x 2
static constexpr uint32_t B_BYTES = 32768;         // 256 x 64 x 2
static constexpr uint32_t STAGE_BYTES = A_BYTES + B_BYTES;      // 48KB
static constexpr uint32_t SMEM_TOTAL = 4 * STAGE_BYTES + 1024;  // 197632

// x converted to fp16 (RN), row-major [8192][4096], packed as uint32 pairs.
__device__ uint32_t g_Xh[8192u * 2048u];           // 64 MB
// Repacked gathered fp16 weights, pre-swizzled 32KB SMEM images:
// image (o, c64): [n=256][k=64] fp16, swz(n*128 + kk*2).  16*20*32KB = 10.5MB
__device__ uint32_t g_Bp[16 * NKIT * 8192];

// ---------------------------------------------------------------------------
__device__ __forceinline__ uint32_t h2_bits(__half2 h) {
    union { __half2 h; uint32_t u; } cvt;
    cvt.h = h;
    return cvt.u;
}
__device__ __forceinline__ uint32_t smem_u32(const void* p) {
    uint32_t a;
    asm("{ .reg .u64 t; cvta.to.shared.u64 t, %1; cvt.u32.u64 %0, t; }"
        : "=r"(a) : "l"(p));
    return a;
}
__device__ __forceinline__ void cpasync16(uint32_t dst, const void* src) {
    asm volatile("cp.async.cg.shared.global [%0], [%1], 16;"
                 :: "r"(dst), "l"(src) : "memory");
}
__device__ __forceinline__ void cp_commit() {
    asm volatile("cp.async.commit_group;" ::: "memory");
}
template <int N>
__device__ __forceinline__ void cp_wait() {
    asm volatile("cp.async.wait_group %0;" :: "n"(N) : "memory");
}
__device__ __forceinline__ void ldsm4(uint32_t* r, uint32_t a) {
    asm volatile("ldmatrix.sync.aligned.m8n8.x4.shared.b16 {%0,%1,%2,%3}, [%4];"
                 : "=r"(r[0]), "=r"(r[1]), "=r"(r[2]), "=r"(r[3]) : "r"(a));
}
__device__ __forceinline__ void mma_f16(float* c, const uint32_t* a,
                                        uint32_t b0, uint32_t b1) {
    asm volatile(
        "mma.sync.aligned.m16n8k16.row.col.f32.f16.f16.f32 "
        "{%0,%1,%2,%3}, {%4,%5,%6,%7}, {%8,%9}, {%0,%1,%2,%3};"
        : "+f"(c[0]), "+f"(c[1]), "+f"(c[2]), "+f"(c[3])
        : "r"(a[0]), "r"(a[1]), "r"(a[2]), "r"(a[3]), "r"(b0), "r"(b1));
}

// ---------------------------------------------------------------------------
// convert: x f32 -> fp16 (RN) into g_Xh. One block per row of 4096.
// ---------------------------------------------------------------------------
__global__ void __launch_bounds__(256, 4)
convert_kernel(const float* __restrict__ x) {
    const size_t row = blockIdx.x;
    const float4* src = reinterpret_cast<const float4*>(x + row * 4096) +
                        threadIdx.x * 4;
    uint4* dst = reinterpret_cast<uint4*>(g_Xh + row * 2048) +
                 threadIdx.x * 2;                 // FIX: 2 uint4 per thread
    float4 v0 = src[0], v1 = src[1], v2 = src[2], v3 = src[3];
    uint4 o;
    o.x = h2_bits(__floats2half2_rn(v0.x, v0.y));
    o.y = h2_bits(__floats2half2_rn(v0.z, v0.w));
    o.z = h2_bits(__floats2half2_rn(v1.x, v1.y));
    o.w = h2_bits(__floats2half2_rn(v1.z, v1.w));
    dst[0] = o;
    o.x = h2_bits(__floats2half2_rn(v2.x, v2.y));
    o.y = h2_bits(__floats2half2_rn(v2.z, v2.w));
    o.z = h2_bits(__floats2half2_rn(v3.x, v3.y));
    o.w = h2_bits(__floats2half2_rn(v3.z, v3.w));
    dst[1] = o;
}

// ---------------------------------------------------------------------------
// repack: gather + transpose + fp16(RN) weights into pre-swizzled images
//   grid: (ntile=8, kchunk32=8, o*5+a=80), block (32, 8)
// image (o, c64 = a*4 + (c32>>1)), k base within image = (c32&1)*32
// ---------------------------------------------------------------------------
__global__ void __launch_bounds__(256, 4)
repack_kernel(const float* __restrict__ w, const int* __restrict__ fi) {
    const int oa = blockIdx.z;
    const int o = oa / 5, a = oa % 5;
    const int f = fi[o * 5 + a];
    const int g = f / 5, slot = f % 5;
    const int k0 = blockIdx.y * 32;
    const int n0 = blockIdx.x * 32;
    const int c32 = blockIdx.y;

    __shared__ float t[32][33];
    const int tx = threadIdx.x, ty = threadIdx.y;

    #pragma unroll
    for (int i = 0; i < 4; ++i) {
        int k = ty + i * 8;
        t[k][tx] = w[((size_t)(g * 256 + k0 + k) * 5 + slot) * 256 + n0 + tx];
    }
    __syncthreads();

    uint32_t* tile = g_Bp +
        ((size_t)o * NKIT + a * 4 + (c32 >> 1)) * 8192;
    const int kb = (c32 & 1) * 32;
    const int tid = ty * 32 + tx;
    const int p  = tid & 15;        // k pair index 0..15 (2 fp16 each)
    const int nn = tid >> 4;        // 0..15
    #pragma unroll
    for (int i = 0; i < 2; ++i) {
        int n = n0 + nn + i * 16;
        uint32_t val = h2_bits(
            __floats2half2_rn(t[2 * p][nn + i * 16], t[2 * p + 1][nn + i * 16]));
        uint32_t off = (uint32_t)n * 128u + (uint32_t)(kb + 2 * p) * 2u;
        uint32_t swz = off ^ ((off >> 3) & 0x70u);
        tile[swz >> 2] = val;
    }
}

// ---------------------------------------------------------------------------
// GEMM: grid (o=16, mtile=64), 256 threads, CTA tile 128(M) x 256(N)
//   8 warps in 2(m) x 4(n) grid of 64x64 warp tiles; fp16 m16n8k16;
//   k=64 per stage, barrier hidden under queued MMA work.
// ---------------------------------------------------------------------------
__global__ void __launch_bounds__(256, 1)
gemm_kernel(const int* __restrict__ fi, float* __restrict__ out) {
    extern __shared__ char smem_raw[];
    const uint32_t sb = (smem_u32(smem_raw) + 1023u) & ~1023u;
    const int tid = (int)threadIdx.x;
    const int wid = tid >> 5;
    const int lane = tid & 31;
    const int o = (int)blockIdx.x;
    const int m_base = (int)blockIdx.y * 128;
    const int warp_m = wid >> 2;   // 0..1  (64 rows each)
    const int warp_n = wid & 3;    // 0..3  (64 cols each)

    int colf[5];
    #pragma unroll
    for (int a = 0; a < 5; ++a) colf[a] = (fi[o * 5 + a] / 5) << 8;  // fp16 elems

    // ---- producer addressing (all 256 threads) ----
    // A: 128 rows x 128B (64 fp16) per stage; 2 threads/row, 4 16B segs each.
    const int arow = tid >> 1;                 // 0..127
    const int asub = (tid & 1) * 4;            // segments asub..asub+3 (of 8)
    const uint32_t* xrow = g_Xh + (size_t)(m_base + arow) * 2048;
    const uint32_t adst_base = (uint32_t)arow * 128u;
    const uint32_t axor = (uint32_t)(arow & 7) << 4;
    // B: 32KB image = 2048 16B segs -> 8 per thread (raw copy)
    const uint32_t* bsrc0 = g_Bp + (size_t)o * NKIT * 8192 + tid * 4;

    auto issue = [&](int it, uint32_t s) {
        const uint32_t st = sb + s * STAGE_BYTES;
        const int col = colf[it >> 2] + (it & 3) * 64;    // fp16 col
        const uint32_t* asrc = xrow + (col >> 1) + asub * 4;
        #pragma unroll
        for (int j = 0; j < 4; ++j) {
            uint32_t doff = (((uint32_t)(asub + j) * 16u) ^ axor);
            cpasync16(st + adst_base + doff, asrc + j * 4);
        }
        const uint32_t* bsrc = bsrc0 + (size_t)it * 8192;
        #pragma unroll
        for (int j = 0; j < 8; ++j)
            cpasync16(st + A_BYTES + (uint32_t)tid * 16u + (uint32_t)j * 4096u,
                      bsrc + j * 1024);
        cp_commit();
    };

    // ---- consumer lane addressing (identical mapping to tf32 version) ----
    const int a_tile = lane >> 3;              // 0..3
    const int a_row_l = ((a_tile & 1) << 3) + (lane & 7);
    const int a_ktile = a_tile >> 1;           // 0..1 (16B half of 32B k-step)
    const int b_khalf = (lane >> 3) & 1;
    const int b_row_l = (((lane >> 4) & 1) << 3) + (lane & 7);

    const uint32_t a_warp_off = (uint32_t)(warp_m * 64) * 128u;
    const uint32_t b_warp_off = A_BYTES + (uint32_t)(warp_n * 64) * 128u;

    float c[4][8][4];
    #pragma unroll
    for (int mi = 0; mi < 4; ++mi)
        #pragma unroll
        for (int ni = 0; ni < 8; ++ni)
            #pragma unroll
            for (int q = 0; q < 4; ++q) c[mi][ni][q] = 0.0f;

    uint32_t af[2][4][4];   // [pingpong][mi][frag]
    uint32_t bf[2][4][4];   // [pingpong][ni2][frag]

    // ks = 0..3: k16 step within the 64-fp16 (128B) stage row.
    auto load_frags = [&](uint32_t st, int ks, int pb) {
        const uint32_t abw = st + a_warp_off;
        const uint32_t bbw = st + b_warp_off;
        #pragma unroll
        for (int mi = 0; mi < 4; ++mi) {
            int row = mi * 16 + a_row_l;
            uint32_t off = (uint32_t)((ks * 2 + a_ktile) * 16) ^
                           ((uint32_t)(row & 7) << 4);
            ldsm4(af[pb][mi], abw + (uint32_t)row * 128u + off);
        }
        #pragma unroll
        for (int ni2 = 0; ni2 < 4; ++ni2) {
            int n = ni2 * 16 + b_row_l;
            uint32_t off = (uint32_t)((ks * 2 + b_khalf) * 16) ^
                           ((uint32_t)(n & 7) << 4);
            ldsm4(bf[pb][ni2], bbw + (uint32_t)n * 128u + off);
        }
    };

    auto mma_group = [&](int pb) {
        #pragma unroll
        for (int mi = 0; mi < 4; ++mi)
            #pragma unroll
            for (int ni = 0; ni < 8; ++ni) {
                const uint32_t* bp = &bf[pb][ni >> 1][(ni & 1) * 2];
                mma_f16(c[mi][ni], af[pb][mi], bp[0], bp[1]);
            }
    };

    // prologue: fill 3 stages, land frags for stage 0 / ks 0
    issue(0, 0); issue(1, 1); issue(2, 2);
    cp_wait<2>();
    __syncthreads();
    load_frags(sb, 0, 0);

    #pragma unroll 4
    for (int it = 0; it < NKIT; ++it) {
        const uint32_t st = sb + (uint32_t)(it & 3) * STAGE_BYTES;

        // entry invariant: pb0 holds ks0 frags of stage it
        load_frags(st, 1, 1);                 // ks1 -> pb1
        mma_group(0);                         // ks0

        if (it + 3 < NKIT) issue(it + 3, (uint32_t)((it + 3) & 3));
        else cp_commit();                     // keep group numbering advancing

        load_frags(st, 2, 0);                 // ks2 -> pb0
        mma_group(1);                         // ks1
        load_frags(st, 3, 1);                 // ks3 -> pb1

        // barrier hidden under the ks2+ks3 tensor queue:
        cp_wait<2>();                         // stage it+1 landed
        __syncthreads();                      // cross-thread visibility + reuse

        mma_group(0);                         // ks2 (regs loaded pre-barrier)
        if (it + 1 < NKIT)
            load_frags(sb + (uint32_t)((it + 1) & 3) * STAGE_BYTES, 0, 0);
        mma_group(1);                         // ks3
    }

    // ---- epilogue: direct stores ----
    const int g = lane >> 2, t4 = lane & 3;
    const int row0 = m_base + warp_m * 64 + g;
    const int col0 = o * 256 + warp_n * 64 + t4 * 2;
    #pragma unroll
    for (int mi = 0; mi < 4; ++mi) {
        #pragma unroll
        for (int ni = 0; ni < 8; ++ni) {
            float* p0 = out + (size_t)(row0 + mi * 16) * 4096 + col0 + ni * 8;
            float* p1 = p0 + 8 * 4096;
            *reinterpret_cast<float2*>(p0) =
                make_float2(c[mi][ni][0], c[mi][ni][1]);
            *reinterpret_cast<float2*>(p1) =
                make_float2(c[mi][ni][2], c[mi][ni][3]);
        }
    }
}

// ---------------------------------------------------------------------------
extern "C" void kernel_launch(void* const* d_in, const int* in_sizes, int n_in,
                              void* d_out, int out_size) {
    const float* x  = (const float*)d_in[0];
    const float* w  = (const float*)d_in[1];
    const int*   fi = (const int*)d_in[2];
    float* out = (float*)d_out;

    convert_kernel<<<8192, 256>>>(x);
    repack_kernel<<<dim3(8, 8, 80), dim3(32, 8)>>>(w, fi);

    cudaFuncSetAttribute(gemm_kernel,
                         cudaFuncAttributeMaxDynamicSharedMemorySize, SMEM_TOTAL);
    gemm_kernel<<<dim3(16, 64), 256, SMEM_TOTAL>>>(fi, out);
}